// round 4
// baseline (speedup 1.0000x reference)
#include <cuda_runtime.h>
#include <cstdint>

#define T_STEPS 128
#define B_SZ    128
#define N_RES   4096
#define IN_DIM  1024
#define MAX_DIM 4608
#define M_A     (T_STEPS * B_SZ)   // 16384 rows for phase A

// ---------------- scratch (device globals; no cudaMalloc allowed) ----------
__device__ float g_P[(size_t)M_A * N_RES];          // input_part, 268 MB
__device__ float g_G[(size_t)M_A * 3 * N_RES];      // gates (post-sigmoid), 805 MB
__device__ float g_state[B_SZ * N_RES];             // exact recurrent state
__device__ float g_state_r[2][B_SZ * N_RES];        // tf32-rounded state, double buffered
__device__ float g_part[4][B_SZ * N_RES];           // K-split partials
__device__ int   g_cnt[T_STEPS][32];                // per (step, n-tile) arrival counters

// pre-rounded (tf32-representable) operand copies
__device__ float g_x_r[(size_t)M_A * IN_DIM];       // 64 MB
__device__ float g_Win_r[(size_t)N_RES * IN_DIM];   // 16 MB
__device__ float g_Wgate_r[(size_t)3 * N_RES * IN_DIM]; // 48 MB
__device__ float g_Wres_r[(size_t)N_RES * N_RES];   // 64 MB

// ---------------- small helpers -------------------------------------------
__device__ __forceinline__ uint32_t cvt_tf32(float x) {
    uint32_t r;
    asm("cvt.rna.tf32.f32 %0, %1;" : "=r"(r) : "f"(x));
    return r;
}

__device__ __forceinline__ void mma_tf32_16x8x8(float* d, const uint32_t* a, const uint32_t* b) {
    asm volatile(
        "mma.sync.aligned.m16n8k8.row.col.f32.tf32.tf32.f32 "
        "{%0,%1,%2,%3}, {%4,%5,%6,%7}, {%8,%9}, {%0,%1,%2,%3};"
        : "+f"(d[0]), "+f"(d[1]), "+f"(d[2]), "+f"(d[3])
        : "r"(a[0]), "r"(a[1]), "r"(a[2]), "r"(a[3]), "r"(b[0]), "r"(b[1]));
}

__device__ __forceinline__ void cp16(void* sm, const void* gm) {
    uint32_t s = (uint32_t)__cvta_generic_to_shared(sm);
    asm volatile("cp.async.cg.shared.global [%0], [%1], 16;" :: "r"(s), "l"(gm));
}
#define CP_COMMIT() asm volatile("cp.async.commit_group;")

// ---------------- pre-rounding --------------------------------------------
__global__ __launch_bounds__(256) void round4_kernel(const float4* __restrict__ src,
                                                     int n4, int which) {
    float4* dst = (which == 0) ? (float4*)g_x_r
                : (which == 1) ? (float4*)g_Win_r
                : (which == 2) ? (float4*)g_Wgate_r
                               : (float4*)g_Wres_r;
    int i = blockIdx.x * 256 + threadIdx.x;
    if (i < n4) {
        float4 v = src[i];
        float4 o;
        o.x = __uint_as_float(cvt_tf32(v.x));
        o.y = __uint_as_float(cvt_tf32(v.y));
        o.z = __uint_as_float(cvt_tf32(v.z));
        o.w = __uint_as_float(cvt_tf32(v.w));
        dst[i] = o;
    }
}

// ===========================================================================
// Phase A: C[m,f] = sum_k X[m,k] * W[f,k]   (M=16384, F=16384, K=1024)
// f < 4096  -> g_P (raw);  f >= 4096 -> g_G (sigmoid applied)
// CTA tile 128x128, 8 warps (2x4), warp tile 64x32, KC=16, double-buffered.
// Operands pre-rounded to tf32 -> no cvt in the hot loop.
// ===========================================================================
__global__ __launch_bounds__(256) void phaseA_gemm() {
    __shared__ uint32_t As[2][128][20];
    __shared__ uint32_t Bs[2][128][20];

    const int tid  = threadIdx.x;
    const int warp = tid >> 5, lane = tid & 31;
    const int g  = lane >> 2, tg = lane & 3;
    const int wm = warp >> 2, wn = warp & 3;            // 2 x 4 warp grid
    const int mbase = blockIdx.y * 128;
    const int fblk  = blockIdx.x;                       // 0..127
    const bool isP  = (fblk < 32);
    const float* W  = isP ? g_Win_r : g_Wgate_r;
    const int frow0 = isP ? fblk * 128 : (fblk - 32) * 128;

    float acc[4][4][4];
    #pragma unroll
    for (int i = 0; i < 4; i++)
        #pragma unroll
        for (int j = 0; j < 4; j++)
            #pragma unroll
            for (int c = 0; c < 4; c++) acc[i][j][c] = 0.f;

    const int NIT = IN_DIM / 16;   // 64

    auto load_stage = [&](int s, int it) {
        const int k0 = it * 16;
        #pragma unroll
        for (int r = 0; r < 2; r++) {
            int c = tid + r * 256;
            int row = c >> 2, seg = c & 3;
            cp16(&As[s][row][seg * 4], g_x_r + (size_t)(mbase + row) * IN_DIM + k0 + seg * 4);
        }
        #pragma unroll
        for (int r = 0; r < 2; r++) {
            int c = tid + r * 256;
            int row = c >> 2, seg = c & 3;
            cp16(&Bs[s][row][seg * 4], W + (size_t)(frow0 + row) * IN_DIM + k0 + seg * 4);
        }
    };

    load_stage(0, 0);
    CP_COMMIT();

    for (int it = 0; it < NIT; it++) {
        const int s = it & 1;
        if (it + 1 < NIT) load_stage(s ^ 1, it + 1);
        CP_COMMIT();
        asm volatile("cp.async.wait_group 1;");
        __syncthreads();

        #pragma unroll
        for (int kk = 0; kk < 16; kk += 8) {
            uint32_t af[4][4], bf[4][2];
            #pragma unroll
            for (int mt = 0; mt < 4; mt++) {
                const int r = wm * 64 + mt * 16 + g;
                af[mt][0] = As[s][r    ][kk + tg    ];
                af[mt][1] = As[s][r + 8][kk + tg    ];
                af[mt][2] = As[s][r    ][kk + tg + 4];
                af[mt][3] = As[s][r + 8][kk + tg + 4];
            }
            #pragma unroll
            for (int nt = 0; nt < 4; nt++) {
                const int fc = wn * 32 + nt * 8 + g;
                bf[nt][0] = Bs[s][fc][kk + tg    ];
                bf[nt][1] = Bs[s][fc][kk + tg + 4];
            }
            #pragma unroll
            for (int mt = 0; mt < 4; mt++)
                #pragma unroll
                for (int nt = 0; nt < 4; nt++)
                    mma_tf32_16x8x8(acc[mt][nt], af[mt], bf[nt]);
        }
        __syncthreads();
    }

    // epilogue
    #pragma unroll
    for (int mt = 0; mt < 4; mt++) {
        #pragma unroll
        for (int nt = 0; nt < 4; nt++) {
            const int fc = fblk * 128 + wn * 32 + nt * 8 + 2 * tg;   // global feature col
            #pragma unroll
            for (int half = 0; half < 2; half++) {
                const int m = mbase + wm * 64 + mt * 16 + g + half * 8;
                const float v0 = acc[mt][nt][half * 2 + 0];
                const float v1 = acc[mt][nt][half * 2 + 1];
                if (isP) {
                    *(float2*)&g_P[(size_t)m * N_RES + fc] = make_float2(v0, v1);
                } else {
                    float2 o = make_float2(1.f / (1.f + __expf(-v0)),
                                           1.f / (1.f + __expf(-v1)));
                    *(float2*)&g_G[(size_t)m * (3 * N_RES) + (fc - N_RES)] = o;
                }
            }
        }
    }
}

// ===========================================================================
// Phase B fused step: GEMM partials + deterministic last-CTA cell update.
// grid = (32 n-tiles, 4 k-splits); 512 threads (16 warps, warp tile 32x32);
// 4-stage cp.async pipeline. Reads g_state_r[t&1], writes g_state_r[(t+1)&1].
// ===========================================================================
#define STEPB_SMEM (4 * (128 * 20 + 16 * 136) * 4)   // 75776 bytes

__global__ __launch_bounds__(512) void stepB_fused(float* __restrict__ out, int t) {
    extern __shared__ uint32_t smem[];
    uint32_t (*As)[128][20]  = (uint32_t(*)[128][20])smem;
    uint32_t (*Bs)[16][136]  = (uint32_t(*)[16][136])(smem + 4 * 128 * 20);
    __shared__ int s_last;

    const int tid  = threadIdx.x;
    const int warp = tid >> 5, lane = tid & 31;
    const int g  = lane >> 2, tg = lane & 3;
    const int wm = warp >> 2, wn = warp & 3;            // 4 x 4 warp grid
    const int nbase = blockIdx.x * 128;
    const int kbase = blockIdx.y * 1024;
    const float* srd = g_state_r[t & 1];

    float acc[2][4][4];
    #pragma unroll
    for (int i = 0; i < 2; i++)
        #pragma unroll
        for (int j = 0; j < 4; j++)
            #pragma unroll
            for (int c = 0; c < 4; c++) acc[i][j][c] = 0.f;

    const int NIT = 64;   // 1024 / 16

    auto load_stage = [&](int s, int it) {
        const int k0 = kbase + it * 16;
        {   // A: 128 rows x 16 k = 512 x 16B
            int row = tid >> 2, seg = tid & 3;
            cp16(&As[s][row][seg * 4], srd + (size_t)row * N_RES + k0 + seg * 4);
        }
        {   // B: 16 k x 128 n = 512 x 16B
            int kr = tid >> 5, seg = tid & 31;
            cp16(&Bs[s][kr][seg * 4], g_Wres_r + (size_t)(k0 + kr) * N_RES + nbase + seg * 4);
        }
    };

    #pragma unroll
    for (int s = 0; s < 3; s++) { load_stage(s, s); CP_COMMIT(); }

    for (int it = 0; it < NIT; it++) {
        const int s = it & 3;
        if (it + 3 < NIT) load_stage((it + 3) & 3, it + 3);
        CP_COMMIT();
        asm volatile("cp.async.wait_group 3;");
        __syncthreads();

        #pragma unroll
        for (int kk = 0; kk < 16; kk += 8) {
            uint32_t af[2][4], bf[4][2];
            #pragma unroll
            for (int mt = 0; mt < 2; mt++) {
                const int r = wm * 32 + mt * 16 + g;
                af[mt][0] = As[s][r    ][kk + tg    ];
                af[mt][1] = As[s][r + 8][kk + tg    ];
                af[mt][2] = As[s][r    ][kk + tg + 4];
                af[mt][3] = As[s][r + 8][kk + tg + 4];
            }
            #pragma unroll
            for (int nt = 0; nt < 4; nt++) {
                const int col = wn * 32 + nt * 8 + g;
                bf[nt][0] = Bs[s][kk + tg    ][col];
                bf[nt][1] = Bs[s][kk + tg + 4][col];
            }
            #pragma unroll
            for (int mt = 0; mt < 2; mt++)
                #pragma unroll
                for (int nt = 0; nt < 4; nt++)
                    mma_tf32_16x8x8(acc[mt][nt], af[mt], bf[nt]);
        }
        __syncthreads();
    }

    // ---- write this k-split's partial -------------------------------------
    float* part = g_part[blockIdx.y];
    #pragma unroll
    for (int mt = 0; mt < 2; mt++) {
        #pragma unroll
        for (int nt = 0; nt < 4; nt++) {
            const int n = nbase + wn * 32 + nt * 8 + 2 * tg;
            #pragma unroll
            for (int half = 0; half < 2; half++) {
                const int m = wm * 32 + mt * 16 + g + half * 8;
                *(float2*)&part[(size_t)m * N_RES + n] =
                    make_float2(acc[mt][nt][half * 2 + 0], acc[mt][nt][half * 2 + 1]);
            }
        }
    }

    // ---- release + arrive --------------------------------------------------
    __threadfence();
    __syncthreads();
    if (tid == 0) {
        int old = atomicAdd(&g_cnt[t][blockIdx.x], 1);
        s_last = (old == 3) ? 1 : 0;
    }
    __syncthreads();
    if (!s_last) return;
    __threadfence();   // acquire: other CTAs' partials now visible

    // ---- last CTA for this n-tile: cell update (fixed reduce order) -------
    float* srd_next = g_state_r[(t + 1) & 1];
    const size_t trow = (size_t)t * B_SZ;
    for (int e = tid; e < B_SZ * 128; e += 512) {
        const int b = e >> 7;
        const int n = nbase + (e & 127);
        const int idx = b * N_RES + n;

        const float res = g_part[0][idx] + g_part[1][idx] + g_part[2][idx] + g_part[3][idx];
        const float prev = g_state[idx];

        const size_t mrow = trow + b;
        const float pp = g_P[mrow * N_RES + n];
        const float* gr = g_G + mrow * (3 * N_RES);
        const float gi = gr[n];
        const float gf = gr[N_RES + n];
        const float go = gr[2 * N_RES + n];

        const float z = gi * (pp + res);
        float sv = 0.9f * gf * prev + 0.1f * tanhf(z);
        sv *= go;
        if (sv > 0.5f) sv -= 0.5f;

        g_state[idx] = sv;
        srd_next[idx] = __uint_as_float(cvt_tf32(sv));
        out[mrow * MAX_DIM + n] = sv;
    }
}

// ---------------- init / padding ------------------------------------------
__global__ __launch_bounds__(256) void init_state_kernel(const float* __restrict__ state0) {
    const int n = blockIdx.x * 256 + threadIdx.x;
    const int b = blockIdx.y;
    const float v = state0[(size_t)b * MAX_DIM + n];
    g_state[b * N_RES + n] = v;
    g_state_r[0][b * N_RES + n] = __uint_as_float(cvt_tf32(v));
}

__global__ __launch_bounds__(256) void zero_cnt_kernel() {
    const int i = blockIdx.x * 256 + threadIdx.x;
    ((int*)g_cnt)[i] = 0;   // 128*32 = 4096 ints
}

__global__ __launch_bounds__(256) void pad_out_kernel(float4* __restrict__ out) {
    const int idx = blockIdx.x * 256 + threadIdx.x;   // over T*B*128 float4
    const int tb = idx >> 7;
    const int c = idx & 127;
    out[(size_t)tb * (MAX_DIM / 4) + (N_RES / 4) + c] = make_float4(0.f, 0.f, 0.f, 0.f);
}

// ===========================================================================
extern "C" void kernel_launch(void* const* d_in, const int* in_sizes, int n_in,
                              void* d_out, int out_size) {
    const float* x      = (const float*)d_in[0];   // [T,B,1024]
    const float* state0 = (const float*)d_in[1];   // [B,4608]
    const float* W_res  = (const float*)d_in[2];   // [4096,4096]
    const float* W_in   = (const float*)d_in[3];   // [4096,1024]
    const float* W_gate = (const float*)d_in[4];   // [12288,1024]
    float* out = (float*)d_out;                    // [T,B,4608]

    static bool attr_done = false;
    if (!attr_done) {
        cudaFuncSetAttribute(stepB_fused, cudaFuncAttributeMaxDynamicSharedMemorySize, STEPB_SMEM);
        attr_done = true;
    }

    // pre-round all GEMM operands to tf32-representable floats
    round4_kernel<<<16384, 256>>>((const float4*)x,      (M_A * IN_DIM) / 4,          0);
    round4_kernel<<< 4096, 256>>>((const float4*)W_in,   (N_RES * IN_DIM) / 4,        1);
    round4_kernel<<<12288, 256>>>((const float4*)W_gate, (3 * N_RES * IN_DIM) / 4,    2);
    round4_kernel<<<16384, 256>>>((const float4*)W_res,  (N_RES * N_RES) / 4,         3);

    init_state_kernel<<<dim3(16, 128), 256>>>(state0);
    zero_cnt_kernel<<<16, 256>>>();
    pad_out_kernel<<<8192, 256>>>((float4*)out);

    // Phase A: all input-dependent terms in one big GEMM
    phaseA_gemm<<<dim3(128, 128), 256>>>();

    // Phase B: sequential recurrence (GEMM + fused update per step)
    for (int t = 0; t < T_STEPS; t++) {
        stepB_fused<<<dim3(32, 4), 512, STEPB_SMEM>>>(out, t);
    }
}

// round 5
// speedup vs baseline: 1.3813x; 1.3813x over previous
#include <cuda_runtime.h>
#include <cstdint>

#define T_STEPS 128
#define B_SZ    128
#define N_RES   4096
#define IN_DIM  1024
#define MAX_DIM 4608
#define M_A     (T_STEPS * B_SZ)   // 16384 rows for phase A
#define KSPLIT  8                  // phase-B k-splits (K-chunk 512)

// ---------------- scratch (device globals; no cudaMalloc allowed) ----------
__device__ float g_P[(size_t)M_A * N_RES];          // input_part, 268 MB
__device__ float g_G[(size_t)M_A * 3 * N_RES];      // gates (post-sigmoid), 805 MB
__device__ float g_state[B_SZ * N_RES];             // exact recurrent state
__device__ float g_state_r[B_SZ * N_RES];           // tf32-rounded state (GEMM input)
__device__ float g_part[KSPLIT][B_SZ * N_RES];      // K-split partials, 16 MB

// pre-rounded (tf32-representable) operand copies
__device__ float g_x_r[(size_t)M_A * IN_DIM];           // 64 MB
__device__ float g_Win_r[(size_t)N_RES * IN_DIM];       // 16 MB
__device__ float g_Wgate_r[(size_t)3 * N_RES * IN_DIM]; // 48 MB
__device__ float g_Wres_r[(size_t)N_RES * N_RES];       // 64 MB

// ---------------- small helpers -------------------------------------------
__device__ __forceinline__ uint32_t cvt_tf32(float x) {
    uint32_t r;
    asm("cvt.rna.tf32.f32 %0, %1;" : "=r"(r) : "f"(x));
    return r;
}

__device__ __forceinline__ void mma_tf32_16x8x8(float* d, const uint32_t* a, const uint32_t* b) {
    asm volatile(
        "mma.sync.aligned.m16n8k8.row.col.f32.tf32.tf32.f32 "
        "{%0,%1,%2,%3}, {%4,%5,%6,%7}, {%8,%9}, {%0,%1,%2,%3};"
        : "+f"(d[0]), "+f"(d[1]), "+f"(d[2]), "+f"(d[3])
        : "r"(a[0]), "r"(a[1]), "r"(a[2]), "r"(a[3]), "r"(b[0]), "r"(b[1]));
}

__device__ __forceinline__ void cp16(void* sm, const void* gm) {
    uint32_t s = (uint32_t)__cvta_generic_to_shared(sm);
    asm volatile("cp.async.cg.shared.global [%0], [%1], 16;" :: "r"(s), "l"(gm));
}
#define CP_COMMIT() asm volatile("cp.async.commit_group;")
#define CP_WAIT1()  asm volatile("cp.async.wait_group 1;")

// ---------------- pre-rounding --------------------------------------------
__global__ __launch_bounds__(256) void round4_kernel(const float4* __restrict__ src,
                                                     int n4, int which) {
    float4* dst = (which == 0) ? (float4*)g_x_r
                : (which == 1) ? (float4*)g_Win_r
                : (which == 2) ? (float4*)g_Wgate_r
                               : (float4*)g_Wres_r;
    int i = blockIdx.x * 256 + threadIdx.x;
    if (i < n4) {
        float4 v = src[i];
        float4 o;
        o.x = __uint_as_float(cvt_tf32(v.x));
        o.y = __uint_as_float(cvt_tf32(v.y));
        o.z = __uint_as_float(cvt_tf32(v.z));
        o.w = __uint_as_float(cvt_tf32(v.w));
        dst[i] = o;
    }
}

// ===========================================================================
// Phase A: C[m,f] = sum_k X[m,k] * W[f,k]   (M=16384, F=16384, K=1024)
// f < 4096  -> g_P (raw);  f >= 4096 -> g_G (sigmoid applied)
// CTA tile 128x128, 8 warps (2x4), warp tile 64x32, KC=16, double-buffered.
// Operands pre-rounded to tf32 -> no cvt in the hot loop.
// ===========================================================================
__global__ __launch_bounds__(256) void phaseA_gemm() {
    __shared__ uint32_t As[2][128][20];
    __shared__ uint32_t Bs[2][128][20];

    const int tid  = threadIdx.x;
    const int warp = tid >> 5, lane = tid & 31;
    const int g  = lane >> 2, tg = lane & 3;
    const int wm = warp >> 2, wn = warp & 3;            // 2 x 4 warp grid
    const int mbase = blockIdx.y * 128;
    const int fblk  = blockIdx.x;                       // 0..127
    const bool isP  = (fblk < 32);
    const float* W  = isP ? g_Win_r : g_Wgate_r;
    const int frow0 = isP ? fblk * 128 : (fblk - 32) * 128;

    float acc[4][4][4];
    #pragma unroll
    for (int i = 0; i < 4; i++)
        #pragma unroll
        for (int j = 0; j < 4; j++)
            #pragma unroll
            for (int c = 0; c < 4; c++) acc[i][j][c] = 0.f;

    const int NIT = IN_DIM / 16;   // 64

    auto load_stage = [&](int s, int it) {
        const int k0 = it * 16;
        #pragma unroll
        for (int r = 0; r < 2; r++) {
            int c = tid + r * 256;
            int row = c >> 2, seg = c & 3;
            cp16(&As[s][row][seg * 4], g_x_r + (size_t)(mbase + row) * IN_DIM + k0 + seg * 4);
        }
        #pragma unroll
        for (int r = 0; r < 2; r++) {
            int c = tid + r * 256;
            int row = c >> 2, seg = c & 3;
            cp16(&Bs[s][row][seg * 4], W + (size_t)(frow0 + row) * IN_DIM + k0 + seg * 4);
        }
    };

    load_stage(0, 0);
    CP_COMMIT();

    for (int it = 0; it < NIT; it++) {
        const int s = it & 1;
        if (it + 1 < NIT) load_stage(s ^ 1, it + 1);
        CP_COMMIT();
        CP_WAIT1();
        __syncthreads();

        #pragma unroll
        for (int kk = 0; kk < 16; kk += 8) {
            uint32_t af[4][4], bf[4][2];
            #pragma unroll
            for (int mt = 0; mt < 4; mt++) {
                const int r = wm * 64 + mt * 16 + g;
                af[mt][0] = As[s][r    ][kk + tg    ];
                af[mt][1] = As[s][r + 8][kk + tg    ];
                af[mt][2] = As[s][r    ][kk + tg + 4];
                af[mt][3] = As[s][r + 8][kk + tg + 4];
            }
            #pragma unroll
            for (int nt = 0; nt < 4; nt++) {
                const int fc = wn * 32 + nt * 8 + g;
                bf[nt][0] = Bs[s][fc][kk + tg    ];
                bf[nt][1] = Bs[s][fc][kk + tg + 4];
            }
            #pragma unroll
            for (int mt = 0; mt < 4; mt++)
                #pragma unroll
                for (int nt = 0; nt < 4; nt++)
                    mma_tf32_16x8x8(acc[mt][nt], af[mt], bf[nt]);
        }
        __syncthreads();
    }

    // epilogue
    #pragma unroll
    for (int mt = 0; mt < 4; mt++) {
        #pragma unroll
        for (int nt = 0; nt < 4; nt++) {
            const int fc = fblk * 128 + wn * 32 + nt * 8 + 2 * tg;   // global feature col
            #pragma unroll
            for (int half = 0; half < 2; half++) {
                const int m = mbase + wm * 64 + mt * 16 + g + half * 8;
                const float v0 = acc[mt][nt][half * 2 + 0];
                const float v1 = acc[mt][nt][half * 2 + 1];
                if (isP) {
                    *(float2*)&g_P[(size_t)m * N_RES + fc] = make_float2(v0, v1);
                } else {
                    float2 o = make_float2(1.f / (1.f + __expf(-v0)),
                                           1.f / (1.f + __expf(-v1)));
                    *(float2*)&g_G[(size_t)m * (3 * N_RES) + (fc - N_RES)] = o;
                }
            }
        }
    }
}

// ===========================================================================
// Phase B per-step GEMM: R[m,n] = sum_k state_r[m,k] * W_res[k,n]
// grid = (32 n-tiles, 8 k-splits) = 256 CTAs -> 2 CTAs/SM co-resident.
// CTA tile 128x128, 8 warps (2x4, warp tile 64x32), K-chunk 512, double-buffered.
// ===========================================================================
__global__ __launch_bounds__(256, 2) void stepB_gemm() {
    __shared__ uint32_t As[2][128][20];    // state rows [m][k]
    __shared__ uint32_t Bs[2][16][136];    // W_res tile [k][n]

    const int tid  = threadIdx.x;
    const int warp = tid >> 5, lane = tid & 31;
    const int g  = lane >> 2, tg = lane & 3;
    const int wm = warp >> 2, wn = warp & 3;
    const int nbase = blockIdx.x * 128;
    const int kbase = blockIdx.y * (N_RES / KSPLIT);   // 512 per split

    float acc[4][4][4];
    #pragma unroll
    for (int i = 0; i < 4; i++)
        #pragma unroll
        for (int j = 0; j < 4; j++)
            #pragma unroll
            for (int c = 0; c < 4; c++) acc[i][j][c] = 0.f;

    const int NIT = (N_RES / KSPLIT) / 16;   // 32

    auto load_stage = [&](int s, int it) {
        const int k0 = kbase + it * 16;
        #pragma unroll
        for (int r = 0; r < 2; r++) {
            int c = tid + r * 256;
            int row = c >> 2, seg = c & 3;
            cp16(&As[s][row][seg * 4], g_state_r + (size_t)row * N_RES + k0 + seg * 4);
        }
        #pragma unroll
        for (int r = 0; r < 2; r++) {
            int c = tid + r * 256;
            int kr = c >> 5, seg = c & 31;
            cp16(&Bs[s][kr][seg * 4], g_Wres_r + (size_t)(k0 + kr) * N_RES + nbase + seg * 4);
        }
    };

    load_stage(0, 0);
    CP_COMMIT();

    for (int it = 0; it < NIT; it++) {
        const int s = it & 1;
        if (it + 1 < NIT) load_stage(s ^ 1, it + 1);
        CP_COMMIT();
        CP_WAIT1();
        __syncthreads();

        #pragma unroll
        for (int kk = 0; kk < 16; kk += 8) {
            uint32_t af[4][4], bf[4][2];
            #pragma unroll
            for (int mt = 0; mt < 4; mt++) {
                const int r = wm * 64 + mt * 16 + g;
                af[mt][0] = As[s][r    ][kk + tg    ];
                af[mt][1] = As[s][r + 8][kk + tg    ];
                af[mt][2] = As[s][r    ][kk + tg + 4];
                af[mt][3] = As[s][r + 8][kk + tg + 4];
            }
            #pragma unroll
            for (int nt = 0; nt < 4; nt++) {
                const int col = wn * 32 + nt * 8 + g;
                bf[nt][0] = Bs[s][kk + tg    ][col];
                bf[nt][1] = Bs[s][kk + tg + 4][col];
            }
            #pragma unroll
            for (int mt = 0; mt < 4; mt++)
                #pragma unroll
                for (int nt = 0; nt < 4; nt++)
                    mma_tf32_16x8x8(acc[mt][nt], af[mt], bf[nt]);
        }
        __syncthreads();
    }

    float* part = g_part[blockIdx.y];
    #pragma unroll
    for (int mt = 0; mt < 4; mt++) {
        #pragma unroll
        for (int nt = 0; nt < 4; nt++) {
            const int n = nbase + wn * 32 + nt * 8 + 2 * tg;
            #pragma unroll
            for (int half = 0; half < 2; half++) {
                const int m = wm * 64 + mt * 16 + g + half * 8;
                *(float2*)&part[(size_t)m * N_RES + n] =
                    make_float2(acc[mt][nt][half * 2 + 0], acc[mt][nt][half * 2 + 1]);
            }
        }
    }
}

// ===========================================================================
// Per-step reduce + cell update + output write (deterministic, full-chip)
// ===========================================================================
__global__ __launch_bounds__(256) void update_kernel(float* __restrict__ out, int t) {
    const int n = blockIdx.x * 256 + threadIdx.x;   // 0..4095
    const int b = blockIdx.y;
    const int idx = b * N_RES + n;

    float res = 0.f;
    #pragma unroll
    for (int ks = 0; ks < KSPLIT; ks++) res += g_part[ks][idx];

    const float prev = g_state[idx];

    const size_t mrow = (size_t)t * B_SZ + b;
    const float pp = g_P[mrow * N_RES + n];
    const float* gr = g_G + mrow * (3 * N_RES);
    const float gi = gr[n];
    const float gf = gr[N_RES + n];
    const float go = gr[2 * N_RES + n];

    const float z = gi * (pp + res);
    float s = 0.9f * gf * prev + 0.1f * tanhf(z);
    s *= go;
    if (s > 0.5f) s -= 0.5f;

    g_state[idx]   = s;
    g_state_r[idx] = __uint_as_float(cvt_tf32(s));
    out[mrow * MAX_DIM + n] = s;
}

// ---------------- init / padding ------------------------------------------
__global__ __launch_bounds__(256) void init_state_kernel(const float* __restrict__ state0) {
    const int n = blockIdx.x * 256 + threadIdx.x;
    const int b = blockIdx.y;
    const float v = state0[(size_t)b * MAX_DIM + n];
    g_state[b * N_RES + n]   = v;
    g_state_r[b * N_RES + n] = __uint_as_float(cvt_tf32(v));
}

__global__ __launch_bounds__(256) void pad_out_kernel(float4* __restrict__ out) {
    const int idx = blockIdx.x * 256 + threadIdx.x;   // over T*B*128 float4
    const int tb = idx >> 7;
    const int c = idx & 127;
    out[(size_t)tb * (MAX_DIM / 4) + (N_RES / 4) + c] = make_float4(0.f, 0.f, 0.f, 0.f);
}

// ===========================================================================
extern "C" void kernel_launch(void* const* d_in, const int* in_sizes, int n_in,
                              void* d_out, int out_size) {
    const float* x      = (const float*)d_in[0];   // [T,B,1024]
    const float* state0 = (const float*)d_in[1];   // [B,4608]
    const float* W_res  = (const float*)d_in[2];   // [4096,4096]
    const float* W_in   = (const float*)d_in[3];   // [4096,1024]
    const float* W_gate = (const float*)d_in[4];   // [12288,1024]
    float* out = (float*)d_out;                    // [T,B,4608]

    // pre-round all GEMM operands to tf32-representable floats
    round4_kernel<<<16384, 256>>>((const float4*)x,      (M_A * IN_DIM) / 4,          0);
    round4_kernel<<< 4096, 256>>>((const float4*)W_in,   (N_RES * IN_DIM) / 4,        1);
    round4_kernel<<<12288, 256>>>((const float4*)W_gate, (3 * N_RES * IN_DIM) / 4,    2);
    round4_kernel<<<16384, 256>>>((const float4*)W_res,  (N_RES * N_RES) / 4,         3);

    init_state_kernel<<<dim3(16, 128), 256>>>(state0);
    pad_out_kernel<<<8192, 256>>>((float4*)out);

    // Phase A: all input-dependent terms in one big GEMM
    phaseA_gemm<<<dim3(128, 128), 256>>>();

    // Phase B: sequential recurrence
    for (int t = 0; t < T_STEPS; t++) {
        stepB_gemm<<<dim3(32, KSPLIT), 256>>>();
        update_kernel<<<dim3(16, 128), 256>>>(out, t);
    }
}

// round 7
// speedup vs baseline: 1.4078x; 1.0192x over previous
#include <cuda_runtime.h>
#include <cstdint>

#define T_STEPS 128
#define B_SZ    128
#define N_RES   4096
#define IN_DIM  1024
#define MAX_DIM 4608
#define M_A     (T_STEPS * B_SZ)   // 16384 rows for phase A
#define KSPLIT  8                  // phase-B k-splits (K-chunk 512)
#define A_CHUNK_TILES 8            // phaseA m-tiles (=timesteps) per chunk
#define N_CHUNKS (T_STEPS / A_CHUNK_TILES)   // 16

// ---------------- scratch (device globals; no cudaMalloc allowed) ----------
__device__ float g_P[(size_t)M_A * N_RES];          // input_part, 268 MB
__device__ float g_G[(size_t)M_A * 3 * N_RES];      // gates (post-sigmoid), 805 MB
__device__ float g_state[B_SZ * N_RES];             // exact recurrent state
__device__ float g_state_r[B_SZ * N_RES];           // tf32-rounded state (GEMM input)
__device__ float g_part[KSPLIT][B_SZ * N_RES];      // K-split partials, 16 MB

// pre-rounded (tf32-representable) operand copies
__device__ float g_x_r[(size_t)M_A * IN_DIM];           // 64 MB
__device__ float g_Win_r[(size_t)N_RES * IN_DIM];       // 16 MB
__device__ float g_Wgate_r[(size_t)3 * N_RES * IN_DIM]; // 48 MB
__device__ float g_Wres_r[(size_t)N_RES * N_RES];       // 64 MB

// ---------------- small helpers -------------------------------------------
__device__ __forceinline__ uint32_t cvt_tf32(float x) {
    uint32_t r;
    asm("cvt.rna.tf32.f32 %0, %1;" : "=r"(r) : "f"(x));
    return r;
}

__device__ __forceinline__ void mma_tf32_16x8x8(float* d, const uint32_t* a, const uint32_t* b) {
    asm volatile(
        "mma.sync.aligned.m16n8k8.row.col.f32.tf32.tf32.f32 "
        "{%0,%1,%2,%3}, {%4,%5,%6,%7}, {%8,%9}, {%0,%1,%2,%3};"
        : "+f"(d[0]), "+f"(d[1]), "+f"(d[2]), "+f"(d[3])
        : "r"(a[0]), "r"(a[1]), "r"(a[2]), "r"(a[3]), "r"(b[0]), "r"(b[1]));
}

__device__ __forceinline__ void cp16(void* sm, const void* gm) {
    uint32_t s = (uint32_t)__cvta_generic_to_shared(sm);
    asm volatile("cp.async.cg.shared.global [%0], [%1], 16;" :: "r"(s), "l"(gm));
}
#define CP_COMMIT() asm volatile("cp.async.commit_group;")
#define CP_WAIT1()  asm volatile("cp.async.wait_group 1;")

// ---------------- pre-rounding --------------------------------------------
__global__ __launch_bounds__(256) void round4_kernel(const float4* __restrict__ src,
                                                     int n4, int which) {
    float4* dst = (which == 0) ? (float4*)g_x_r
                : (which == 1) ? (float4*)g_Win_r
                : (which == 2) ? (float4*)g_Wgate_r
                               : (float4*)g_Wres_r;
    int i = blockIdx.x * 256 + threadIdx.x;
    if (i < n4) {
        float4 v = src[i];
        float4 o;
        o.x = __uint_as_float(cvt_tf32(v.x));
        o.y = __uint_as_float(cvt_tf32(v.y));
        o.z = __uint_as_float(cvt_tf32(v.z));
        o.w = __uint_as_float(cvt_tf32(v.w));
        dst[i] = o;
    }
}

// ===========================================================================
// Phase A: C[m,f] = sum_k X[m,k] * W[f,k]   (chunked over m-tiles)
// f < 4096  -> g_P (raw);  f >= 4096 -> g_G (sigmoid applied)
// CTA tile 128x128, 8 warps (2x4), warp tile 64x32, KC=16, double-buffered.
// ===========================================================================
__global__ __launch_bounds__(256) void phaseA_gemm(int tile0) {
    __shared__ uint32_t As[2][128][20];
    __shared__ uint32_t Bs[2][128][20];

    const int tid  = threadIdx.x;
    const int warp = tid >> 5, lane = tid & 31;
    const int g  = lane >> 2, tg = lane & 3;
    const int wm = warp >> 2, wn = warp & 3;            // 2 x 4 warp grid
    const int mbase = (tile0 + blockIdx.y) * 128;
    const int fblk  = blockIdx.x;                       // 0..127
    const bool isP  = (fblk < 32);
    const float* W  = isP ? g_Win_r : g_Wgate_r;
    const int frow0 = isP ? fblk * 128 : (fblk - 32) * 128;

    float acc[4][4][4];
    #pragma unroll
    for (int i = 0; i < 4; i++)
        #pragma unroll
        for (int j = 0; j < 4; j++)
            #pragma unroll
            for (int c = 0; c < 4; c++) acc[i][j][c] = 0.f;

    const int NIT = IN_DIM / 16;   // 64

    auto load_stage = [&](int s, int it) {
        const int k0 = it * 16;
        #pragma unroll
        for (int r = 0; r < 2; r++) {
            int c = tid + r * 256;
            int row = c >> 2, seg = c & 3;
            cp16(&As[s][row][seg * 4], g_x_r + (size_t)(mbase + row) * IN_DIM + k0 + seg * 4);
        }
        #pragma unroll
        for (int r = 0; r < 2; r++) {
            int c = tid + r * 256;
            int row = c >> 2, seg = c & 3;
            cp16(&Bs[s][row][seg * 4], W + (size_t)(frow0 + row) * IN_DIM + k0 + seg * 4);
        }
    };

    load_stage(0, 0);
    CP_COMMIT();

    for (int it = 0; it < NIT; it++) {
        const int s = it & 1;
        if (it + 1 < NIT) load_stage(s ^ 1, it + 1);
        CP_COMMIT();
        CP_WAIT1();
        __syncthreads();

        #pragma unroll
        for (int kk = 0; kk < 16; kk += 8) {
            uint32_t af[4][4], bf[4][2];
            #pragma unroll
            for (int mt = 0; mt < 4; mt++) {
                const int r = wm * 64 + mt * 16 + g;
                af[mt][0] = As[s][r    ][kk + tg    ];
                af[mt][1] = As[s][r + 8][kk + tg    ];
                af[mt][2] = As[s][r    ][kk + tg + 4];
                af[mt][3] = As[s][r + 8][kk + tg + 4];
            }
            #pragma unroll
            for (int nt = 0; nt < 4; nt++) {
                const int fc = wn * 32 + nt * 8 + g;
                bf[nt][0] = Bs[s][fc][kk + tg    ];
                bf[nt][1] = Bs[s][fc][kk + tg + 4];
            }
            #pragma unroll
            for (int mt = 0; mt < 4; mt++)
                #pragma unroll
                for (int nt = 0; nt < 4; nt++)
                    mma_tf32_16x8x8(acc[mt][nt], af[mt], bf[nt]);
        }
        __syncthreads();
    }

    // epilogue
    #pragma unroll
    for (int mt = 0; mt < 4; mt++) {
        #pragma unroll
        for (int nt = 0; nt < 4; nt++) {
            const int fc = fblk * 128 + wn * 32 + nt * 8 + 2 * tg;   // global feature col
            #pragma unroll
            for (int half = 0; half < 2; half++) {
                const int m = mbase + wm * 64 + mt * 16 + g + half * 8;
                const float v0 = acc[mt][nt][half * 2 + 0];
                const float v1 = acc[mt][nt][half * 2 + 1];
                if (isP) {
                    *(float2*)&g_P[(size_t)m * N_RES + fc] = make_float2(v0, v1);
                } else {
                    float2 o = make_float2(1.f / (1.f + __expf(-v0)),
                                           1.f / (1.f + __expf(-v1)));
                    *(float2*)&g_G[(size_t)m * (3 * N_RES) + (fc - N_RES)] = o;
                }
            }
        }
    }
}

// ===========================================================================
// Phase B per-step GEMM: R[m,n] = sum_k state_r[m,k] * W_res[k,n]
// grid = (32 n-tiles, 8 k-splits) = 256 CTAs -> 2 CTAs/SM co-resident.
// CTA tile 128x128, 8 warps (2x4, warp tile 64x32), K-chunk 512, double-buffered.
// ===========================================================================
__global__ __launch_bounds__(256, 2) void stepB_gemm() {
    __shared__ uint32_t As[2][128][20];    // state rows [m][k]
    __shared__ uint32_t Bs[2][16][136];    // W_res tile [k][n]

    const int tid  = threadIdx.x;
    const int warp = tid >> 5, lane = tid & 31;
    const int g  = lane >> 2, tg = lane & 3;
    const int wm = warp >> 2, wn = warp & 3;
    const int nbase = blockIdx.x * 128;
    const int kbase = blockIdx.y * (N_RES / KSPLIT);   // 512 per split

    float acc[4][4][4];
    #pragma unroll
    for (int i = 0; i < 4; i++)
        #pragma unroll
        for (int j = 0; j < 4; j++)
            #pragma unroll
            for (int c = 0; c < 4; c++) acc[i][j][c] = 0.f;

    const int NIT = (N_RES / KSPLIT) / 16;   // 32

    auto load_stage = [&](int s, int it) {
        const int k0 = kbase + it * 16;
        #pragma unroll
        for (int r = 0; r < 2; r++) {
            int c = tid + r * 256;
            int row = c >> 2, seg = c & 3;
            cp16(&As[s][row][seg * 4], g_state_r + (size_t)row * N_RES + k0 + seg * 4);
        }
        #pragma unroll
        for (int r = 0; r < 2; r++) {
            int c = tid + r * 256;
            int kr = c >> 5, seg = c & 31;
            cp16(&Bs[s][kr][seg * 4], g_Wres_r + (size_t)(k0 + kr) * N_RES + nbase + seg * 4);
        }
    };

    load_stage(0, 0);
    CP_COMMIT();

    for (int it = 0; it < NIT; it++) {
        const int s = it & 1;
        if (it + 1 < NIT) load_stage(s ^ 1, it + 1);
        CP_COMMIT();
        CP_WAIT1();
        __syncthreads();

        #pragma unroll
        for (int kk = 0; kk < 16; kk += 8) {
            uint32_t af[4][4], bf[4][2];
            #pragma unroll
            for (int mt = 0; mt < 4; mt++) {
                const int r = wm * 64 + mt * 16 + g;
                af[mt][0] = As[s][r    ][kk + tg    ];
                af[mt][1] = As[s][r + 8][kk + tg    ];
                af[mt][2] = As[s][r    ][kk + tg + 4];
                af[mt][3] = As[s][r + 8][kk + tg + 4];
            }
            #pragma unroll
            for (int nt = 0; nt < 4; nt++) {
                const int col = wn * 32 + nt * 8 + g;
                bf[nt][0] = Bs[s][kk + tg    ][col];
                bf[nt][1] = Bs[s][kk + tg + 4][col];
            }
            #pragma unroll
            for (int mt = 0; mt < 4; mt++)
                #pragma unroll
                for (int nt = 0; nt < 4; nt++)
                    mma_tf32_16x8x8(acc[mt][nt], af[mt], bf[nt]);
        }
        __syncthreads();
    }

    float* part = g_part[blockIdx.y];
    #pragma unroll
    for (int mt = 0; mt < 4; mt++) {
        #pragma unroll
        for (int nt = 0; nt < 4; nt++) {
            const int n = nbase + wn * 32 + nt * 8 + 2 * tg;
            #pragma unroll
            for (int half = 0; half < 2; half++) {
                const int m = wm * 64 + mt * 16 + g + half * 8;
                *(float2*)&part[(size_t)m * N_RES + n] =
                    make_float2(acc[mt][nt][half * 2 + 0], acc[mt][nt][half * 2 + 1]);
            }
        }
    }
}

// ===========================================================================
// Per-step reduce + cell update + output write (deterministic, full-chip)
// ===========================================================================
__global__ __launch_bounds__(256) void update_kernel(float* __restrict__ out, int t) {
    const int n = blockIdx.x * 256 + threadIdx.x;   // 0..4095
    const int b = blockIdx.y;
    const int idx = b * N_RES + n;

    float res = 0.f;
    #pragma unroll
    for (int ks = 0; ks < KSPLIT; ks++) res += g_part[ks][idx];

    const float prev = g_state[idx];

    const size_t mrow = (size_t)t * B_SZ + b;
    const float pp = g_P[mrow * N_RES + n];
    const float* gr = g_G + mrow * (3 * N_RES);
    const float gi = gr[n];
    const float gf = gr[N_RES + n];
    const float go = gr[2 * N_RES + n];

    const float z = gi * (pp + res);
    float s = 0.9f * gf * prev + 0.1f * tanhf(z);
    s *= go;
    if (s > 0.5f) s -= 0.5f;

    g_state[idx]   = s;
    g_state_r[idx] = __uint_as_float(cvt_tf32(s));
    out[mrow * MAX_DIM + n] = s;
}

// ---------------- init / padding ------------------------------------------
__global__ __launch_bounds__(256) void init_state_kernel(const float* __restrict__ state0) {
    const int n = blockIdx.x * 256 + threadIdx.x;
    const int b = blockIdx.y;
    const float v = state0[(size_t)b * MAX_DIM + n];
    g_state[b * N_RES + n]   = v;
    g_state_r[b * N_RES + n] = __uint_as_float(cvt_tf32(v));
}

__global__ __launch_bounds__(256) void pad_out_kernel(float4* __restrict__ out) {
    const int idx = blockIdx.x * 256 + threadIdx.x;   // over T*B*128 float4
    const int tb = idx >> 7;
    const int c = idx & 127;
    out[(size_t)tb * (MAX_DIM / 4) + (N_RES / 4) + c] = make_float4(0.f, 0.f, 0.f, 0.f);
}

// ===========================================================================
extern "C" void kernel_launch(void* const* d_in, const int* in_sizes, int n_in,
                              void* d_out, int out_size) {
    const float* x      = (const float*)d_in[0];   // [T,B,1024]
    const float* state0 = (const float*)d_in[1];   // [B,4608]
    const float* W_res  = (const float*)d_in[2];   // [4096,4096]
    const float* W_in   = (const float*)d_in[3];   // [4096,1024]
    const float* W_gate = (const float*)d_in[4];   // [12288,1024]
    float* out = (float*)d_out;                    // [T,B,4608]

    // ---- lazy stream/event setup (only outside capture; never device mem) --
    static cudaStream_t s2 = nullptr;
    static cudaEvent_t evFork = nullptr;
    static cudaEvent_t evChunk[N_CHUNKS];
    static bool setup_tried = false;
    static bool overlap_ok = false;
    if (!setup_tried) {
        setup_tried = true;
        cudaStreamCaptureStatus cap = cudaStreamCaptureStatusNone;
        cudaStreamIsCapturing(0, &cap);
        if (cap == cudaStreamCaptureStatusNone) {
            bool ok = (cudaStreamCreateWithFlags(&s2, cudaStreamNonBlocking) == cudaSuccess);
            ok = ok && (cudaEventCreateWithFlags(&evFork, cudaEventDisableTiming) == cudaSuccess);
            for (int c = 0; ok && c < N_CHUNKS; c++)
                ok = (cudaEventCreateWithFlags(&evChunk[c], cudaEventDisableTiming) == cudaSuccess);
            overlap_ok = ok;
        }
    }

    // ---- main stream: operand pre-rounding + state init -------------------
    round4_kernel<<<16384, 256>>>((const float4*)x,      (M_A * IN_DIM) / 4,          0);
    round4_kernel<<< 4096, 256>>>((const float4*)W_in,   (N_RES * IN_DIM) / 4,        1);
    round4_kernel<<<12288, 256>>>((const float4*)W_gate, (3 * N_RES * IN_DIM) / 4,    2);
    round4_kernel<<<16384, 256>>>((const float4*)W_res,  (N_RES * N_RES) / 4,         3);
    init_state_kernel<<<dim3(16, 128), 256>>>(state0);
    pad_out_kernel<<<8192, 256>>>((float4*)out);

    if (overlap_ok) {
        // ---- fork: phase A runs concurrently on s2, chunked by timestep ----
        cudaEventRecord(evFork, 0);
        cudaStreamWaitEvent(s2, evFork, 0);
        for (int c = 0; c < N_CHUNKS; c++) {
            phaseA_gemm<<<dim3(128, A_CHUNK_TILES), 256, 0, s2>>>(c * A_CHUNK_TILES);
            cudaEventRecord(evChunk[c], s2);
        }

        // ---- phase B on the main stream; join s2 at each chunk boundary ----
        for (int t = 0; t < T_STEPS; t++) {
            stepB_gemm<<<dim3(32, KSPLIT), 256>>>();
            if ((t % A_CHUNK_TILES) == 0)
                cudaStreamWaitEvent(0, evChunk[t / A_CHUNK_TILES], 0);
            update_kernel<<<dim3(16, 128), 256>>>(out, t);
        }
    } else {
        // ---- fallback: fully serial (identical to the passing R4 kernel) ---
        for (int c = 0; c < N_CHUNKS; c++)
            phaseA_gemm<<<dim3(128, A_CHUNK_TILES), 256>>>(c * A_CHUNK_TILES);
        for (int t = 0; t < T_STEPS; t++) {
            stepB_gemm<<<dim3(32, KSPLIT), 256>>>();
            update_kernel<<<dim3(16, 128), 256>>>(out, t);
        }
    }
}